// round 3
// baseline (speedup 1.0000x reference)
#include <cuda_runtime.h>
#include <cstdint>
#include <cstddef>

#define DI __device__ __forceinline__

// ---------------- problem constants ----------------
namespace {
constexpr int BN    = 128;
constexpr int CINc  = 64;
constexpr int NFc   = 16;
constexpr int COUTc = 256;
constexpr int Hc    = 20;
constexpr int Wc    = 20;
constexpr int HWc   = Hc * Wc;          // 400
constexpr int Kc    = CINc * NFc;       // 1024
constexpr int PP    = 21;               // padded spatial extent (index 20 == zero slot)
constexpr int PLANE = PP * PP * BN;     // floats per cin plane (56448)

constexpr int KCHUNK  = 32;             // K per smem stage
constexpr int NCHUNKS = Kc / KCHUNK;    // 32

constexpr int A_CH = 128 * KCHUNK;      // 4096 words per A stage
constexpr int B_CH = COUTc * KCHUNK;    // 8192 words per B stage
constexpr int SMEM_WORDS = 2 * A_CH + 2 * B_CH;   // 24576 words = 96 KB
constexpr int SMEM_BYTES = SMEM_WORDS * 4;

struct Tap { int4 off; float4 w; };
}

// ---------------- device scratch (no allocations allowed) ----------------
__device__ float    d_xt[(size_t)CINc * PLANE];      // 14.5 MB, b-contiguous planes
__device__ float    d_g[(size_t)BN * HWc * COUTc];   // 52.4 MB, [b][hw][o]
__device__ Tap      d_taps[HWc * NFc];               // 200 KB
__device__ uint32_t d_comb_p[COUTc * Kc];            // comb as tf32, k-permuted

// ---------------- small asm helpers ----------------
DI uint32_t smem_u32(const void* p) {
    uint32_t a;
    asm("{ .reg .u64 t; cvta.to.shared.u64 t, %1; cvt.u32.u64 %0, t; }"
        : "=r"(a) : "l"(p));
    return a;
}

DI uint32_t f2tf32(float f) {
    uint32_t u;
    asm("cvt.rna.tf32.f32 %0, %1;" : "=r"(u) : "f"(f));
    return u;
}

DI void cp_async16(uint32_t saddr, const void* gptr) {
    asm volatile("cp.async.cg.shared.global [%0], [%1], 16;"
                 :: "r"(saddr), "l"(gptr));
}
DI void cp_commit() { asm volatile("cp.async.commit_group;" ::: "memory"); }
DI void cp_wait0()  { asm volatile("cp.async.wait_group 0;"  ::: "memory"); }

// m16n8k8 tf32 MMA, fp32 accumulate (sm_80+, works on base sm_100 target)
DI void mma_tf32(float d[4], const uint32_t a[4], uint32_t b0, uint32_t b1) {
    asm volatile(
        "mma.sync.aligned.m16n8k8.row.col.f32.tf32.tf32.f32 "
        "{%0,%1,%2,%3}, {%4,%5,%6,%7}, {%8,%9}, {%0,%1,%2,%3};"
        : "+f"(d[0]), "+f"(d[1]), "+f"(d[2]), "+f"(d[3])
        : "r"(a[0]), "r"(a[1]), "r"(a[2]), "r"(a[3]), "r"(b0), "r"(b1));
}

// ---------------- kernel 1: x (B,CIN,H,W) -> xt[cin][21][21][b] ----------------
// Row/col index 20 is the zero slot. Gather indices are pre-clamped in the tap
// table: ix<0 -> data row 0 (clamp), ix>=20 -> slot 20 (zero). Matches the
// reference's clip(ix,0,20) into a zero-padded array.
__global__ void __launch_bounds__(256) xt_kernel(const float* __restrict__ x) {
    __shared__ float tile[BN * PP];   // [b][j]
    const int cin = blockIdx.x;
    const int i   = blockIdx.y;       // 0..20
    const int tid = threadIdx.x;
    float* dst = d_xt + (size_t)cin * PLANE + (size_t)i * PP * BN;

    if (i == Hc) {                    // zero row
        for (int p = tid; p < PP * BN; p += 256) dst[p] = 0.0f;
        return;
    }
    for (int p = tid; p < BN * Wc; p += 256) {
        int b = p / Wc, j = p % Wc;
        tile[b * PP + j] = x[(((size_t)b * CINc + cin) * Hc + i) * Wc + j];
    }
    __syncthreads();
    for (int p = tid; p < PP * BN; p += 256) {
        int j = p / BN, b = p % BN;
        dst[(size_t)j * BN + b] = (j < Wc) ? tile[b * PP + j] : 0.0f;
    }
}

// ---------------- kernel 2: tap table (offsets + bilinear weights) -------------
__global__ void __launch_bounds__(256) taps_kernel(const float* __restrict__ flow) {
    int id = blockIdx.x * 256 + threadIdx.x;
    if (id >= HWc * NFc) return;
    int hw = id / NFc, nf = id % NFc;
    int h = hw / Wc, w = hw % Wc;

    float f0 = flow[(((size_t)nf * Hc + h) * Wc + w) * 2 + 0];
    float f1 = flow[(((size_t)nf * Hc + h) * Wc + w) * 2 + 1];
    float ix = (float)h + f0;
    float iy = (float)w + f1;
    float bx = floorf(ix), by = floorf(iy);
    float s = ix - bx, t = iy - by;
    int ibx = (int)bx, iby = (int)by;

    int px0 = min(max(ibx,     0), Hc);
    int px1 = min(max(ibx + 1, 0), Hc);
    int py0 = min(max(iby,     0), Wc);
    int py1 = min(max(iby + 1, 0), Wc);

    Tap tp;
    tp.off = make_int4((px0 * PP + py0) * BN,
                       (px1 * PP + py0) * BN,
                       (px0 * PP + py1) * BN,
                       (px1 * PP + py1) * BN);
    float w01 = s * (1.0f - t);   // NOTE: also used for the (bx, by+1) tap (source bug)
    tp.w = make_float4((1.0f - s) * (1.0f - t), w01, w01, s * t);
    d_taps[hw * NFc + nf] = tp;
}

// ---------------- kernel 3: comb -> tf32, k-permuted within 8-blocks -----------
// Within each block of 8 k: value j stored at (j<4 ? 2j : 2j-7). This makes the
// B fragment (b0 = k=c, b1 = k=c+4) a single LDS.64 at word offset 2c.
__global__ void __launch_bounds__(256) combp_kernel(const float* __restrict__ comb) {
    int idx = blockIdx.x * 256 + threadIdx.x;
    if (idx >= COUTc * Kc) return;
    int kk = idx & (Kc - 1);
    int j = kk & 7, base = kk & ~7;
    int pos = (j < 4) ? base + 2 * j : base + 2 * j - 7;
    d_comb_p[(idx & ~(Kc - 1)) + pos] = f2tf32(comb[idx]);
}

// ---------------- kernel 4: per-pixel fused gather + tf32 mma.sync GEMM --------
// One CTA per pixel hw. 512 threads = 16 warps, warp grid 4(M) x 4(N),
// warp tile 32x64, D[128 b][256 o] over K=1024 in 32 chunks of 32.
__global__ void __launch_bounds__(512, 1) gemm_kernel() {
    extern __shared__ uint32_t smem[];
    __shared__ Tap taps_sm[NFc];

    const int hw   = blockIdx.x;
    const int tid  = threadIdx.x;
    const int lane = tid & 31;
    const int wid  = tid >> 5;
    const int wm   = wid & 3;              // M tile (32 rows)
    const int wn   = wid >> 2;             // N tile (64 cols)
    const int lq   = lane >> 2;            // 0..7
    const int lc   = lane & 3;             // 0..3

    const int ktile = tid >> 7;            // A-build role: which k-octet of chunk
    const int rr    = tid & 127;           // A-build row (= batch b)

    uint32_t* As[2] = { smem,              smem + A_CH };
    uint32_t* Bs[2] = { smem + 2 * A_CH,   smem + 2 * A_CH + B_CH };

    if (tid < NFc) taps_sm[tid] = d_taps[hw * NFc + tid];
    __syncthreads();

    // cin for this thread's A-build slice at chunk c: c*2 + (ktile>>1)
    const int cin_off = ktile >> 1;
    // nf indices for the 8 k's are chunk-independent:
    const int nf_base = (ktile * 8) & 15;

    float acc[2][8][4];
    #pragma unroll
    for (int mi = 0; mi < 2; ++mi)
        #pragma unroll
        for (int nj = 0; nj < 8; ++nj)
            #pragma unroll
            for (int e = 0; e < 4; ++e) acc[mi][nj][e] = 0.0f;

    // ---- helpers as lambdas ----
    auto build_a = [&](int chunk, float v[8]) {
        const int cin = chunk * 2 + cin_off;
        const float* __restrict__ plane = d_xt + (size_t)cin * PLANE + rr;
        #pragma unroll
        for (int j = 0; j < 8; ++j) {
            Tap tp = taps_sm[nf_base + j];
            v[j] = plane[tp.off.x] * tp.w.x + plane[tp.off.y] * tp.w.y
                 + plane[tp.off.z] * tp.w.z + plane[tp.off.w] * tp.w.w;
        }
    };
    auto sts_a = [&](uint32_t* Ab, const float v[8]) {
        // pair (j, j+4) -> one 8B store at word 2j; frag LDS.64 reads (a, a2)
        #pragma unroll
        for (int j = 0; j < 4; ++j) {
            uint2 pk = make_uint2(f2tf32(v[j]), f2tf32(v[j + 4]));
            *reinterpret_cast<uint2*>(Ab + ktile * 1024 + rr * 8 + 2 * j) = pk;
        }
    };
    auto issue_b = [&](int chunk, uint32_t* Bb) {
        // 1024 cells of 32B: cell = (ks, o); each thread does 2 cells
        #pragma unroll
        for (int rep = 0; rep < 2; ++rep) {
            int cell = tid + rep * 512;
            int ks = cell >> 8, o = cell & 255;
            const uint32_t* src = d_comb_p + (size_t)o * Kc + chunk * KCHUNK + ks * 8;
            uint32_t dst = smem_u32(Bb + ks * 2048 + o * 8);
            cp_async16(dst,     src);
            cp_async16(dst + 16, src + 4);
        }
    };
    auto mma_chunk = [&](const uint32_t* Ab, const uint32_t* Bb) {
        #pragma unroll
        for (int ks = 0; ks < 4; ++ks) {
            uint32_t a[2][4];
            #pragma unroll
            for (int mi = 0; mi < 2; ++mi) {
                int r0 = wm * 32 + mi * 16 + lq;
                uint2 lo = *reinterpret_cast<const uint2*>(Ab + ks * 1024 + r0 * 8 + 2 * lc);
                uint2 hi = *reinterpret_cast<const uint2*>(Ab + ks * 1024 + (r0 + 8) * 8 + 2 * lc);
                a[mi][0] = lo.x; a[mi][1] = hi.x; a[mi][2] = lo.y; a[mi][3] = hi.y;
            }
            #pragma unroll
            for (int nj = 0; nj < 8; ++nj) {
                int n = wn * 64 + nj * 8 + lq;
                uint2 bb = *reinterpret_cast<const uint2*>(Bb + ks * 2048 + n * 8 + 2 * lc);
                mma_tf32(acc[0][nj], a[0], bb.x, bb.y);
                mma_tf32(acc[1][nj], a[1], bb.x, bb.y);
            }
        }
    };

    // ---- software pipeline ----
    float vstage[8];
    build_a(0, vstage);
    issue_b(0, Bs[0]);
    sts_a(As[0], vstage);
    cp_commit();
    cp_wait0();
    __syncthreads();

    for (int c = 0; c < NCHUNKS; ++c) {
        const int p = c & 1, q = p ^ 1;
        const bool more = (c + 1 < NCHUNKS);
        if (more) {
            build_a(c + 1, vstage);      // 32 LDGs batch up front, hidden by MMA below
            issue_b(c + 1, Bs[q]);
            cp_commit();
        }
        mma_chunk(As[p], Bs[p]);
        if (more) {
            sts_a(As[q], vstage);
            cp_wait0();
        }
        __syncthreads();
    }

    // ---- writeback: 32B-sector-aligned float2 stores into d_g[b][hw][o] ----
    #pragma unroll
    for (int mi = 0; mi < 2; ++mi) {
        int r0 = wm * 32 + mi * 16 + lq;
        #pragma unroll
        for (int nj = 0; nj < 8; ++nj) {
            int o0 = wn * 64 + nj * 8 + 2 * lc;
            *reinterpret_cast<float2*>(&d_g[((size_t)r0 * HWc + hw) * COUTc + o0]) =
                make_float2(acc[mi][nj][0], acc[mi][nj][1]);
            *reinterpret_cast<float2*>(&d_g[((size_t)(r0 + 8) * HWc + hw) * COUTc + o0]) =
                make_float2(acc[mi][nj][2], acc[mi][nj][3]);
        }
    }
}

// ---------------- kernel 5: g[b][hw][o] -> out[b][o][hw] + bias ----------------
__global__ void __launch_bounds__(256) trans_kernel(const float* __restrict__ bias,
                                                    float* __restrict__ out) {
    __shared__ float tile[32][33];
    const int tx = threadIdx.x;        // 0..31
    const int ty = threadIdx.y;        // 0..7
    const int ht = blockIdx.x;         // hw tile (13)
    const int ot = blockIdx.y;         // o tile (8)
    const int b  = blockIdx.z;         // 128

    #pragma unroll
    for (int k = 0; k < 4; ++k) {
        int hw = ht * 32 + ty + k * 8;
        int o  = ot * 32 + tx;
        if (hw < HWc)
            tile[ty + k * 8][tx] = d_g[((size_t)b * HWc + hw) * COUTc + o];
    }
    __syncthreads();
    #pragma unroll
    for (int k = 0; k < 4; ++k) {
        int o  = ot * 32 + ty + k * 8;
        int hw = ht * 32 + tx;
        if (hw < HWc)
            out[((size_t)b * COUTc + o) * HWc + hw] = tile[tx][ty + k * 8] + bias[o];
    }
}

// ---------------- launch ----------------
extern "C" void kernel_launch(void* const* d_in, const int* in_sizes, int n_in,
                              void* d_out, int out_size) {
    const float* x    = (const float*)d_in[0];   // (128, 64, 20, 20)
    const float* flow = (const float*)d_in[1];   // (16, 20, 20, 2)
    const float* comb = (const float*)d_in[2];   // (256, 1024)
    const float* bias = (const float*)d_in[3];   // (256,)
    float* out = (float*)d_out;                  // (128, 256, 20, 20)

    cudaFuncSetAttribute(gemm_kernel,
                         cudaFuncAttributeMaxDynamicSharedMemorySize, SMEM_BYTES);

    xt_kernel<<<dim3(CINc, PP), 256>>>(x);
    taps_kernel<<<(HWc * NFc + 255) / 256, 256>>>(flow);
    combp_kernel<<<(COUTc * Kc + 255) / 256, 256>>>(comb);
    gemm_kernel<<<HWc, 512, SMEM_BYTES>>>();
    trans_kernel<<<dim3(13, 8, BN), dim3(32, 8)>>>(bias, out);
}